// round 2
// baseline (speedup 1.0000x reference)
#include <cuda_runtime.h>

// SwitchLinear: out[t] = (W[route[t]] + Wf) @ x[t] + b[route[t]] + bf
// B=4096, IN=OUT=256, E=16, fp32.
//
// prep_kernel  (129 blocks): block 0 = route histogram/scan/scatter + tile table;
//                            blocks 1..128 = Wsum = W + Wf, TRANSPOSED to [e][k][o].
// switch_gemm  (144 blocks): per (expert, 32-token) tile, 32x256x256 fp32 GEMM.
//   - weights staged k-major via cp.async (double-buffered, 1 sync + wait/iter)
//   - inputs staged as duplicated f32x2 pairs (bank-conflict-free layout)
//   - math in packed fma.rn.f32x2 (FFMA2): 16 FFMA2 per k per thread

#define B_TOK   4096
#define E_NUM   16
#define IN_DIM  256
#define OUT_DIM 256
#define TILE_T  32
#define KC      16
#define NC      (IN_DIM / KC)     // 16 chunks
#define MAX_TILES 160
#define GRID_GEMM 144

__device__ int   g_sorted[B_TOK];
__device__ int   g_tile_e[MAX_TILES];
__device__ int   g_tile_base[MAX_TILES];
__device__ int   g_tile_cnt[MAX_TILES];
__device__ int   g_ntiles;
__device__ float g_wsumT[E_NUM * IN_DIM * OUT_DIM];   // [e][k][o], 4 MB scratch

#define FMA2(c, a, b) \
    asm("fma.rn.f32x2 %0, %1, %2, %0;" : "+l"(c) : "l"(a), "l"(b))

#define CP_ASYNC16(dst_u32, src_ptr) \
    asm volatile("cp.async.cg.shared.global [%0], [%1], 16;" :: "r"(dst_u32), "l"(src_ptr))
#define CP_COMMIT()  asm volatile("cp.async.commit_group;" ::: "memory")
#define CP_WAIT0()   asm volatile("cp.async.wait_group 0;" ::: "memory")

// ---------------------------------------------------------------------------
// prep: routing table (block 0) + transposed weight-sum (blocks 1..128)
// ---------------------------------------------------------------------------
__global__ void prep_kernel(const int* __restrict__ route,
                            const float* __restrict__ weight,
                            const float* __restrict__ wfact) {
    const int tid = threadIdx.x;

    if (blockIdx.x == 0) {
        __shared__ int cnt[E_NUM];
        __shared__ int cur[E_NUM];
        const int lane = tid & 31;
        if (tid < E_NUM) cnt[tid] = 0;
        __syncthreads();

        for (int t = tid; t < B_TOK; t += 256) {
            int e = route[t];
            unsigned m = __match_any_sync(0xffffffffu, e);
            int leader = __ffs(m) - 1;
            if (lane == leader) atomicAdd(&cnt[e], __popc(m));
        }
        __syncthreads();

        if (tid < 32) {  // warp 0: parallel tile table via warp scans
            int c  = (tid < E_NUM) ? cnt[tid] : 0;
            int nt = (c + TILE_T - 1) / TILE_T;
            int cs = c, ts = nt;
            #pragma unroll
            for (int d = 1; d < 32; d <<= 1) {
                int v = __shfl_up_sync(0xffffffffu, cs, d);
                int w = __shfl_up_sync(0xffffffffu, ts, d);
                if (lane >= d) { cs += v; ts += w; }
            }
            int coff = cs - c, toff = ts - nt;
            if (tid < E_NUM) {
                cur[tid] = coff;
                for (int j = 0; j < nt; j++) {
                    g_tile_e[toff + j]    = tid;
                    g_tile_base[toff + j] = coff + j * TILE_T;
                    int rem = c - j * TILE_T;
                    g_tile_cnt[toff + j]  = rem < TILE_T ? rem : TILE_T;
                }
                if (tid == E_NUM - 1) g_ntiles = ts;
            }
        }
        __syncthreads();

        for (int t = tid; t < B_TOK; t += 256) {
            int e = route[t];
            unsigned m = __match_any_sync(0xffffffffu, e);
            int leader = __ffs(m) - 1;
            int rank = __popc(m & ((1u << lane) - 1u));
            int base = 0;
            if (lane == leader) base = atomicAdd(&cur[e], __popc(m));
            base = __shfl_sync(m, base, leader);
            g_sorted[base + rank] = t;
        }
    } else {
        // transpose+add: 1024 (32x32) tiles over 128 blocks, 8 tiles each
        __shared__ float s[32][33];
        const int bb = blockIdx.x - 1;
        const int ol = tid >> 3, kv = tid & 7;   // read role
        const int kl = tid >> 3, ov = tid & 7;   // write role
        #pragma unroll 1
        for (int i = 0; i < 8; i++) {
            int gt = bb * 8 + i;
            int e = gt >> 6, rem = gt & 63;
            int ob = (rem >> 3) * 32, kb = (rem & 7) * 32;
            const float4 w4 = *(const float4*)(weight + (size_t)e * 65536 + (size_t)(ob + ol) * 256 + kb + kv * 4);
            const float4 f4 = *(const float4*)(wfact + (size_t)(ob + ol) * 256 + kb + kv * 4);
            s[ol][kv * 4 + 0] = w4.x + f4.x;
            s[ol][kv * 4 + 1] = w4.y + f4.y;
            s[ol][kv * 4 + 2] = w4.z + f4.z;
            s[ol][kv * 4 + 3] = w4.w + f4.w;
            __syncthreads();
            float4 o4;
            o4.x = s[ov * 4 + 0][kl];
            o4.y = s[ov * 4 + 1][kl];
            o4.z = s[ov * 4 + 2][kl];
            o4.w = s[ov * 4 + 3][kl];
            *(float4*)(g_wsumT + (size_t)e * 65536 + (size_t)(kb + kl) * 256 + ob + ov * 4) = o4;
            __syncthreads();
        }
    }
}

// ---------------------------------------------------------------------------
// gemm: one block per 32-token tile. 256 threads.
//   thread: og = tid>>2 (outputs og*4..+3 = 2 f32x2 pairs), tg = tid&3
//           tokens tg*8..tg*8+7 -> 16 f32x2 accumulators
//   per k per warp: 1 LDS.128 weight (128B bcast, 1 phase)
//                 + 4 LDS.128 input dup-pairs (1 phase each) + 16 FFMA2
// ---------------------------------------------------------------------------
__global__ __launch_bounds__(256, 1)
void switch_gemm(const float* __restrict__ input,
                 const float* __restrict__ bias,
                 const float* __restrict__ bfact,
                 float* __restrict__ out) {
    const int bid = blockIdx.x;
    if (bid >= g_ntiles) return;
    const int tid = threadIdx.x;

    const int e     = g_tile_e[bid];
    const int tbase = g_tile_base[bid];
    const int tcnt  = g_tile_cnt[bid];

    __shared__ float  w_s[2][KC * OUT_DIM];      // 2 x 16 KB, [k][o] chunk (contiguous copy)
    __shared__ float2 in_s[2][KC][4][12];        // dup pairs, stride 12 => conflict-free 16B lanes
    __shared__ int    toks[TILE_T];

    if (tid < TILE_T) {
        int i = (tid < tcnt) ? tid : (tcnt - 1);
        toks[tid] = g_sorted[tbase + i];
    }
    __syncthreads();

    const int og = tid >> 2;          // 0..63
    const int tg = tid & 3;           // 0..3

    // loader roles
    const int lt  = tid >> 3;         // token 0..31
    const int lk  = tid & 7;          // k-pair 0..7 (k_local = lk*2, lk*2+1)
    const int ltg = lt >> 3, lpr = lt & 7;
    const float* __restrict__ wsrc = g_wsumT + (size_t)e * 65536;
    const float* __restrict__ irow = input + (size_t)toks[lt] * IN_DIM;

    const unsigned ws_base = (unsigned)__cvta_generic_to_shared(&w_s[0][0]);

    unsigned long long acc[8][2];
    #pragma unroll
    for (int j = 0; j < 8; j++) { acc[j][0] = 0ull; acc[j][1] = 0ull; }

    // ---- stage weight chunk c into buffer b via cp.async (16 KB contiguous)
    auto stage_w = [&](int c, int b) {
        unsigned dst = ws_base + (unsigned)(b * (KC * OUT_DIM * 4)) + tid * 16u;
        const float* src = wsrc + c * (KC * OUT_DIM) + tid * 4;
        #pragma unroll
        for (int i = 0; i < 4; i++)
            CP_ASYNC16(dst + i * 4096u, src + i * 1024);
        CP_COMMIT();
    };
    auto sts_in = [&](int b, float2 iv) {
        float2 d0 = make_float2(iv.x, iv.x);
        float2 d1 = make_float2(iv.y, iv.y);
        in_s[b][lk * 2 + 0][ltg][lpr] = d0;
        in_s[b][lk * 2 + 1][ltg][lpr] = d1;
    };

    // prologue
    stage_w(0, 0);
    float2 iv = *(const float2*)(irow + 0 * KC + lk * 2);
    sts_in(0, iv);
    iv = *(const float2*)(irow + 1 * KC + lk * 2);

    #pragma unroll 1
    for (int c = 0; c < NC; c++) {
        CP_WAIT0();
        __syncthreads();                     // chunk c (w + in) visible; prev compute done
        if (c + 1 < NC) {
            stage_w(c + 1, (c + 1) & 1);     // overlaps with compute(c)
            sts_in((c + 1) & 1, iv);
        }
        if (c + 2 < NC)
            iv = *(const float2*)(irow + (c + 2) * KC + lk * 2);

        const float* wb = &w_s[c & 1][0];
        #pragma unroll
        for (int k = 0; k < KC; k++) {
            ulonglong2 w01 = *(const ulonglong2*)(wb + k * OUT_DIM + og * 4);
            const float2* ip = &in_s[c & 1][k][tg][0];
            ulonglong2 iA = *(const ulonglong2*)(ip + 0);
            ulonglong2 iB = *(const ulonglong2*)(ip + 2);
            ulonglong2 iC = *(const ulonglong2*)(ip + 4);
            ulonglong2 iD = *(const ulonglong2*)(ip + 6);
            FMA2(acc[0][0], iA.x, w01.x);  FMA2(acc[0][1], iA.x, w01.y);
            FMA2(acc[1][0], iA.y, w01.x);  FMA2(acc[1][1], iA.y, w01.y);
            FMA2(acc[2][0], iB.x, w01.x);  FMA2(acc[2][1], iB.x, w01.y);
            FMA2(acc[3][0], iB.y, w01.x);  FMA2(acc[3][1], iB.y, w01.y);
            FMA2(acc[4][0], iC.x, w01.x);  FMA2(acc[4][1], iC.x, w01.y);
            FMA2(acc[5][0], iC.y, w01.x);  FMA2(acc[5][1], iC.y, w01.y);
            FMA2(acc[6][0], iD.x, w01.x);  FMA2(acc[6][1], iD.x, w01.y);
            FMA2(acc[7][0], iD.y, w01.x);  FMA2(acc[7][1], iD.y, w01.y);
        }
    }

    // epilogue: bias + store (float4 per token)
    const float4 b4  = *(const float4*)(bias + e * OUT_DIM + og * 4);
    const float4 bf4 = *(const float4*)(bfact + og * 4);
    float4 bsum;
    bsum.x = b4.x + bf4.x;  bsum.y = b4.y + bf4.y;
    bsum.z = b4.z + bf4.z;  bsum.w = b4.w + bf4.w;

    #pragma unroll
    for (int tt = 0; tt < 8; tt++) {
        int t = tg * 8 + tt;
        if (t < tcnt) {
            float2 p0 = *(float2*)&acc[tt][0];
            float2 p1 = *(float2*)&acc[tt][1];
            float4 o;
            o.x = p0.x + bsum.x;  o.y = p0.y + bsum.y;
            o.z = p1.x + bsum.z;  o.w = p1.y + bsum.w;
            *(float4*)(out + (size_t)toks[t] * OUT_DIM + og * 4) = o;
        }
    }
}

// ---------------------------------------------------------------------------
extern "C" void kernel_launch(void* const* d_in, const int* in_sizes, int n_in,
                              void* d_out, int out_size) {
    const float* input  = (const float*)d_in[0];
    const int*   route  = (const int*)d_in[1];
    const float* weight = (const float*)d_in[2];
    const float* wfact  = (const float*)d_in[3];
    const float* bias   = (const float*)d_in[4];
    const float* bfact  = (const float*)d_in[5];
    float* out = (float*)d_out;

    prep_kernel<<<129, 256>>>(route, weight, wfact);
    switch_gemm<<<GRID_GEMM, 256>>>(input, bias, bfact, out);
}

// round 4
// speedup vs baseline: 1.1626x; 1.1626x over previous
#include <cuda_runtime.h>

// SwitchLinear: out[t] = (W[route[t]] + Wf) @ x[t] + b[route[t]] + bf
// B=4096, IN=OUT=256, E=16, fp32.
//
// prep (513 blocks): block 512 = routing (histogram/scan/scatter + tile table);
//                    blocks 0..511 = Wsum = W + Wf transposed to [e][k][o].
// switch_gemm (144 blocks, 256 thr): per (expert, 32-token) tile.
//   Warp split: 4 out-quarters x 2 token-halves. Thread: 8 adjacent outs
//   (4 f32x2 pairs, non-dup LDS.128) x 4 tokens (dup f32x2 LDS.64 bcast).
//   16 FFMA2 vs 6 LDS wavefronts per warp per k -> FMA-pipe bound.

#define B_TOK   4096
#define E_NUM   16
#define IN_DIM  256
#define OUT_DIM 256
#define TILE_T  32
#define KC      32
#define NC      (IN_DIM / KC)        // 8 chunks
#define MAX_TILES 160
#define GRID_GEMM 144
#define W_GROUPS  32                 // 32 groups of 8 outs per k-row
#define W_GSTRIDE 12                 // 8 data + 4 pad floats: bank-quad perfect spread
#define W_ROW     (W_GROUPS * W_GSTRIDE)   // 384 floats per k-row
#define ID_STRIDE 33                 // in_dup row stride (float2 units)

__device__ int   g_sorted[B_TOK];
__device__ int   g_tile_e[MAX_TILES];
__device__ int   g_tile_base[MAX_TILES];
__device__ int   g_tile_cnt[MAX_TILES];
__device__ int   g_ntiles;
__device__ float g_wsumT[E_NUM * IN_DIM * OUT_DIM];   // [e][k][o]

#define FMA2(c, a, b) \
    asm("fma.rn.f32x2 %0, %1, %2, %0;" : "+l"(c) : "l"(a), "l"(b))

#define CP_ASYNC16(dst_u32, src_ptr) \
    asm volatile("cp.async.cg.shared.global [%0], [%1], 16;" :: "r"(dst_u32), "l"(src_ptr))
#define CP_COMMIT()  asm volatile("cp.async.commit_group;" ::: "memory")
#define CP_WAIT0()   asm volatile("cp.async.wait_group 0;" ::: "memory")

// ---------------------------------------------------------------------------
// prep: blocks 0..511 transpose Wsum (2 32x32 tiles each); block 512 = routing
// ---------------------------------------------------------------------------
__global__ void prep_kernel(const int* __restrict__ route,
                            const float* __restrict__ weight,
                            const float* __restrict__ wfact) {
    const int tid = threadIdx.x;

    if (blockIdx.x < 512) {
        __shared__ float s[32][33];
        const int ol = tid >> 3, kv = tid & 7;
        const int kl = tid >> 3, ov = tid & 7;
        #pragma unroll
        for (int i = 0; i < 2; i++) {
            int gt = blockIdx.x * 2 + i;            // 0..1023 tiles
            int e = gt >> 6, rem = gt & 63;
            int ob = (rem >> 3) * 32, kb = (rem & 7) * 32;
            const float4 w4 = *(const float4*)(weight + (size_t)e * 65536 + (size_t)(ob + ol) * 256 + kb + kv * 4);
            const float4 f4 = *(const float4*)(wfact + (size_t)(ob + ol) * 256 + kb + kv * 4);
            s[ol][kv * 4 + 0] = w4.x + f4.x;
            s[ol][kv * 4 + 1] = w4.y + f4.y;
            s[ol][kv * 4 + 2] = w4.z + f4.z;
            s[ol][kv * 4 + 3] = w4.w + f4.w;
            __syncthreads();
            float4 o4;
            o4.x = s[ov * 4 + 0][kl];
            o4.y = s[ov * 4 + 1][kl];
            o4.z = s[ov * 4 + 2][kl];
            o4.w = s[ov * 4 + 3][kl];
            *(float4*)(g_wsumT + (size_t)e * 65536 + (size_t)(kb + kl) * 256 + ob + ov * 4) = o4;
            __syncthreads();
        }
    } else {
        __shared__ int cnt[E_NUM];
        __shared__ int cur[E_NUM];
        const int lane = tid & 31;
        if (tid < E_NUM) cnt[tid] = 0;
        __syncthreads();

        for (int t = tid; t < B_TOK; t += 256) {
            int e = route[t];
            unsigned m = __match_any_sync(0xffffffffu, e);
            int leader = __ffs(m) - 1;
            if (lane == leader) atomicAdd(&cnt[e], __popc(m));
        }
        __syncthreads();

        if (tid < 32) {
            int c  = (tid < E_NUM) ? cnt[tid] : 0;
            int nt = (c + TILE_T - 1) / TILE_T;
            int cs = c, ts = nt;
            #pragma unroll
            for (int d = 1; d < 32; d <<= 1) {
                int v = __shfl_up_sync(0xffffffffu, cs, d);
                int w = __shfl_up_sync(0xffffffffu, ts, d);
                if (lane >= d) { cs += v; ts += w; }
            }
            int coff = cs - c, toff = ts - nt;
            if (tid < E_NUM) {
                cur[tid] = coff;
                for (int j = 0; j < nt; j++) {
                    g_tile_e[toff + j]    = tid;
                    g_tile_base[toff + j] = coff + j * TILE_T;
                    int rem = c - j * TILE_T;
                    g_tile_cnt[toff + j]  = rem < TILE_T ? rem : TILE_T;
                }
                if (tid == E_NUM - 1) g_ntiles = ts;
            }
        }
        __syncthreads();

        for (int t = tid; t < B_TOK; t += 256) {
            int e = route[t];
            unsigned m = __match_any_sync(0xffffffffu, e);
            int leader = __ffs(m) - 1;
            int rank = __popc(m & ((1u << lane) - 1u));
            int base = 0;
            if (lane == leader) base = atomicAdd(&cur[e], __popc(m));
            base = __shfl_sync(m, base, leader);
            g_sorted[base + rank] = t;
        }
    }
}

// ---------------------------------------------------------------------------
// gemm
// ---------------------------------------------------------------------------
__global__ __launch_bounds__(256, 1)
void switch_gemm(const float* __restrict__ input,
                 const float* __restrict__ bias,
                 const float* __restrict__ bfact,
                 float* __restrict__ out) {
    const int bid = blockIdx.x;
    if (bid >= g_ntiles) return;
    const int tid = threadIdx.x;

    const int e     = g_tile_e[bid];
    const int tbase = g_tile_base[bid];
    const int tcnt  = g_tile_cnt[bid];

    __shared__ float  w_s[2][KC * W_ROW];          // 2 x 48 KB (padded groups)
    __shared__ float2 in_s[2][KC * ID_STRIDE];     // dup pairs, 2 x 8.25 KB
    __shared__ int    toks[TILE_T];

    if (tid < TILE_T) {
        int i = (tid < tcnt) ? tid : (tcnt - 1);
        toks[tid] = g_sorted[tbase + i];
    }
    __syncthreads();

    // compute roles: warp = (oq, th); lane = (og, tg)
    const int wid = tid >> 5;
    const int oq  = wid & 3;          // out quarter (64 outs)
    const int th  = wid >> 2;         // token half (16 tokens)
    const int og  = tid & 7;          // out group of 8 within quarter
    const int tg  = (tid >> 3) & 3;   // token group of 4 within half

    const int wcol  = (oq * 8 + og) * W_GSTRIDE;         // float offset in k-row
    const int itok0 = th * 16 + tg * 4;                  // first of 4 tokens
    const int obase = oq * 64 + og * 8;                  // first of 8 outs

    // loader roles
    const int lt = tid >> 3;          // token 0..31
    const int lk = tid & 7;           // k-quad 0..7
    const float* __restrict__ wsrc = g_wsumT + (size_t)e * 65536;
    const float* __restrict__ irow = input + (size_t)toks[lt] * IN_DIM;

    const unsigned ws_base = (unsigned)__cvta_generic_to_shared(&w_s[0][0]);

    unsigned long long acc[4][4];
    #pragma unroll
    for (int tt = 0; tt < 4; tt++)
        #pragma unroll
        for (int p = 0; p < 4; p++) acc[tt][p] = 0ull;

    // stage weight chunk c (32 k-rows x 256 outs) into padded layout, buffer b
    auto stage_w = [&](int c, int b) {
        const float* src0 = wsrc + c * (KC * OUT_DIM);
        unsigned dst0 = ws_base + (unsigned)(b * (KC * W_ROW * 4));
        #pragma unroll
        for (int i = 0; i < 8; i++) {
            int j = tid + 256 * i;            // 0..2047
            int k = j >> 6;                   // 0..31
            int r = j & 63;                   // 64 x 16B per k-row
            int g = r >> 1, h = r & 1;
            CP_ASYNC16(dst0 + (unsigned)((k * W_ROW + g * W_GSTRIDE + h * 4) * 4),
                       src0 + k * OUT_DIM + g * 8 + h * 4);
        }
        CP_COMMIT();
    };
    auto sts_in = [&](int b, float4 v) {
        float2* d = &in_s[b][0];
        d[(lk * 4 + 0) * ID_STRIDE + lt] = make_float2(v.x, v.x);
        d[(lk * 4 + 1) * ID_STRIDE + lt] = make_float2(v.y, v.y);
        d[(lk * 4 + 2) * ID_STRIDE + lt] = make_float2(v.z, v.z);
        d[(lk * 4 + 3) * ID_STRIDE + lt] = make_float2(v.w, v.w);
    };

    // prologue: chunk0 staged, chunk1 input in flight
    stage_w(0, 0);
    float4 iv = *(const float4*)(irow + 0 * KC + lk * 4);
    sts_in(0, iv);
    iv = *(const float4*)(irow + 1 * KC + lk * 4);

    #pragma unroll 1
    for (int c = 0; c < NC; c++) {
        CP_WAIT0();
        __syncthreads();
        if (c + 1 < NC) {
            stage_w(c + 1, (c + 1) & 1);
            sts_in((c + 1) & 1, iv);
        }
        if (c + 2 < NC)
            iv = *(const float4*)(irow + (c + 2) * KC + lk * 4);

        const float*  wb = &w_s[c & 1][0];
        const float2* ib = &in_s[c & 1][0];
        #pragma unroll
        for (int k = 0; k < KC; k++) {
            float4 wA = *(const float4*)(wb + k * W_ROW + wcol);
            float4 wB = *(const float4*)(wb + k * W_ROW + wcol + 4);
            unsigned long long p0 = *(const unsigned long long*)&wA.x;
            unsigned long long p1 = *(const unsigned long long*)&wA.z;
            unsigned long long p2 = *(const unsigned long long*)&wB.x;
            unsigned long long p3 = *(const unsigned long long*)&wB.z;
            const float2* ik = ib + k * ID_STRIDE + itok0;
            unsigned long long d0 = *(const unsigned long long*)(ik + 0);
            unsigned long long d1 = *(const unsigned long long*)(ik + 1);
            unsigned long long d2 = *(const unsigned long long*)(ik + 2);
            unsigned long long d3 = *(const unsigned long long*)(ik + 3);
            FMA2(acc[0][0], d0, p0); FMA2(acc[0][1], d0, p1);
            FMA2(acc[0][2], d0, p2); FMA2(acc[0][3], d0, p3);
            FMA2(acc[1][0], d1, p0); FMA2(acc[1][1], d1, p1);
            FMA2(acc[1][2], d1, p2); FMA2(acc[1][3], d1, p3);
            FMA2(acc[2][0], d2, p0); FMA2(acc[2][1], d2, p1);
            FMA2(acc[2][2], d2, p2); FMA2(acc[2][3], d2, p3);
            FMA2(acc[3][0], d3, p0); FMA2(acc[3][1], d3, p1);
            FMA2(acc[3][2], d3, p2); FMA2(acc[3][3], d3, p3);
        }
    }

    // epilogue: bias + store, 8 adjacent outs per thread
    const float4 b0  = *(const float4*)(bias + e * OUT_DIM + obase);
    const float4 b1  = *(const float4*)(bias + e * OUT_DIM + obase + 4);
    const float4 f0  = *(const float4*)(bfact + obase);
    const float4 f1  = *(const float4*)(bfact + obase + 4);
    float4 s0, s1;
    s0.x = b0.x + f0.x; s0.y = b0.y + f0.y; s0.z = b0.z + f0.z; s0.w = b0.w + f0.w;
    s1.x = b1.x + f1.x; s1.y = b1.y + f1.y; s1.z = b1.z + f1.z; s1.w = b1.w + f1.w;

    #pragma unroll
    for (int tt = 0; tt < 4; tt++) {
        int t = itok0 + tt;
        if (t < tcnt) {
            float2 a0 = *(float2*)&acc[tt][0];
            float2 a1 = *(float2*)&acc[tt][1];
            float2 a2 = *(float2*)&acc[tt][2];
            float2 a3 = *(float2*)&acc[tt][3];
            float4 o0, o1;
            o0.x = a0.x + s0.x;  o0.y = a0.y + s0.y;
            o0.z = a1.x + s0.z;  o0.w = a1.y + s0.w;
            o1.x = a2.x + s1.x;  o1.y = a2.y + s1.y;
            o1.z = a3.x + s1.z;  o1.w = a3.y + s1.w;
            float* dst = out + (size_t)toks[t] * OUT_DIM + obase;
            *(float4*)(dst + 0) = o0;
            *(float4*)(dst + 4) = o1;
        }
    }
}

// ---------------------------------------------------------------------------
extern "C" void kernel_launch(void* const* d_in, const int* in_sizes, int n_in,
                              void* d_out, int out_size) {
    const float* input  = (const float*)d_in[0];
    const int*   route  = (const int*)d_in[1];
    const float* weight = (const float*)d_in[2];
    const float* wfact  = (const float*)d_in[3];
    const float* bias   = (const float*)d_in[4];
    const float* bfact  = (const float*)d_in[5];
    float* out = (float*)d_out;

    prep_kernel<<<513, 256>>>(route, weight, wfact);
    switch_gemm<<<GRID_GEMM, 256>>>(input, bias, bfact, out);
}

// round 6
// speedup vs baseline: 1.4667x; 1.2615x over previous
#include <cuda_runtime.h>
#include <cstdint>

// SwitchLinear via portable tensor-core mma.sync (tf32), sm_103-safe PTX.
// out[t] = (W[route[t]] + Wf) @ x[t] + b[route[t]] + bf ; B=4096, IN=OUT=256, E=16.
//
// prep (129 blocks): 0..127: g_wsum = cvt.rna.tf32(W + Wf), layout [e][o][k]
//                    (rows are directly the col-major B operand of mma row.col).
//                    128: routing into 128-token m-tiles + g_bsum = bias + bf.
// gemm (96 blocks, 256 thr): tile = (128 tokens, 128 outs).
//   8 warps (4 m x 2 n), warp tile 32x64, mma.m16n8k8.tf32, fp32 accum.
//   K chunks of 32 double-buffered in smem; rows padded to 36 floats
//   (all fragment LDS conflict-free). A: LDG+cvt.rna+STS; B: cp.async.

#define B_TOK   4096
#define E_NUM   16
#define TM      128
#define TN      128
#define KC      32
#define NCH     8
#define MAX_MT  48
#define GRID_GEMM 96
#define RPAD    36                       // floats per padded row
#define TILE_F  (128 * RPAD)             // 4608 floats per tile buffer
#define DSMEM_BYTES (4 * TILE_F * 4)     // A0,A1,B0,B1 = 73728 B

__device__ int   g_sorted[B_TOK];
__device__ int   g_mt_e[MAX_MT];
__device__ int   g_mt_base[MAX_MT];
__device__ int   g_mt_cnt[MAX_MT];
__device__ int   g_nmt;
__device__ float g_wsum[E_NUM * 256 * 256];   // [e][o][k], tf32(rna)-rounded
__device__ float g_bsum[E_NUM * 256];

static __device__ __forceinline__ uint32_t smem_u32(const void* p) {
    uint32_t a;
    asm("{ .reg .u64 t; cvta.to.shared.u64 t, %1; cvt.u32.u64 %0, t; }" : "=r"(a) : "l"(p));
    return a;
}
static __device__ __forceinline__ uint32_t f2tf(float x) {
    uint32_t u;
    asm("cvt.rna.tf32.f32 %0, %1;" : "=r"(u) : "f"(x));
    return u;
}

#define CP_ASYNC16(dst, src) \
    asm volatile("cp.async.cg.shared.global [%0], [%1], 16;" :: "r"(dst), "l"(src))
#define CP_COMMIT() asm volatile("cp.async.commit_group;" ::: "memory")
#define CP_WAIT(n)  asm volatile("cp.async.wait_group %0;" :: "n"(n) : "memory")

static __device__ __forceinline__ void mma_tf32(float* d, const uint32_t* a,
                                                uint32_t b0, uint32_t b1) {
    asm volatile(
        "mma.sync.aligned.m16n8k8.row.col.f32.tf32.tf32.f32 "
        "{%0,%1,%2,%3}, {%4,%5,%6,%7}, {%8,%9}, {%0,%1,%2,%3};"
        : "+f"(d[0]), "+f"(d[1]), "+f"(d[2]), "+f"(d[3])
        : "r"(a[0]), "r"(a[1]), "r"(a[2]), "r"(a[3]), "r"(b0), "r"(b1));
}

// ---------------------------------------------------------------------------
// prep
// ---------------------------------------------------------------------------
__global__ void prep_kernel(const int* __restrict__ route,
                            const float* __restrict__ weight,
                            const float* __restrict__ wfact,
                            const float* __restrict__ bias,
                            const float* __restrict__ bfact) {
    const int tid = threadIdx.x;

    if (blockIdx.x < 128) {
        const size_t base = (size_t)blockIdx.x * 8192;   // floats
        const int fb = (blockIdx.x & 7) * 8192;          // offset mod 65536
        #pragma unroll
        for (int i = 0; i < 8; i++) {
            int j = (tid + 256 * i) * 4;
            float4 w = *(const float4*)(weight + base + j);
            float4 f = *(const float4*)(wfact + fb + j);
            uint4 o;
            o.x = f2tf(w.x + f.x);
            o.y = f2tf(w.y + f.y);
            o.z = f2tf(w.z + f.z);
            o.w = f2tf(w.w + f.w);
            *(uint4*)((float*)g_wsum + base + j) = o;
        }
    } else {
        __shared__ int cnt[E_NUM];
        __shared__ int cur[E_NUM];
        const int lane = tid & 31;
        if (tid < E_NUM) cnt[tid] = 0;
        __syncthreads();

        for (int t = tid; t < B_TOK; t += 256) {
            int e = route[t];
            unsigned m = __match_any_sync(0xffffffffu, e);
            int leader = __ffs(m) - 1;
            if (lane == leader) atomicAdd(&cnt[e], __popc(m));
        }
        __syncthreads();

        if (tid < 32) {
            int c  = (tid < E_NUM) ? cnt[tid] : 0;
            int nt = (c + TM - 1) / TM;
            int cs = c, ts = nt;
            #pragma unroll
            for (int d = 1; d < 32; d <<= 1) {
                int v = __shfl_up_sync(0xffffffffu, cs, d);
                int w = __shfl_up_sync(0xffffffffu, ts, d);
                if (lane >= d) { cs += v; ts += w; }
            }
            int coff = cs - c, toff = ts - nt;
            if (tid < E_NUM) {
                cur[tid] = coff;
                for (int j = 0; j < nt; j++) {
                    g_mt_e[toff + j]    = tid;
                    g_mt_base[toff + j] = coff + j * TM;
                    int rem = c - j * TM;
                    g_mt_cnt[toff + j]  = rem < TM ? rem : TM;
                }
                if (tid == E_NUM - 1) g_nmt = ts;
            }
        }
        __syncthreads();

        for (int t = tid; t < B_TOK; t += 256) {
            int e = route[t];
            unsigned m = __match_any_sync(0xffffffffu, e);
            int leader = __ffs(m) - 1;
            int rank = __popc(m & ((1u << lane) - 1u));
            int base = 0;
            if (lane == leader) base = atomicAdd(&cur[e], __popc(m));
            base = __shfl_sync(m, base, leader);
            g_sorted[base + rank] = t;
        }

        for (int i = tid; i < E_NUM * 256; i += 256)
            g_bsum[i] = bias[i] + bfact[i & 255];
    }
}

// ---------------------------------------------------------------------------
// gemm
// ---------------------------------------------------------------------------
__global__ __launch_bounds__(256, 1)
void switch_gemm(const float* __restrict__ input, float* __restrict__ out) {
    const int mt = blockIdx.x >> 1;
    const int nb = blockIdx.x & 1;
    if (mt >= g_nmt) return;

    extern __shared__ float dsm[];
    // layout: A0 [0,4608) A1 [4608,9216) B0 [9216,13824) B1 [13824,18432)
    __shared__ int   toks[TM];
    __shared__ float bias_s[TN];

    const int tid  = threadIdx.x;
    const int wid  = tid >> 5;
    const int lane = tid & 31;
    const int wm   = wid & 3;         // 4 m-warps of 32 tokens
    const int wn   = wid >> 2;        // 2 n-warps of 64 outs
    const int r0   = lane >> 2;       // quad row 0..7
    const int kq   = lane & 3;        // quad k 0..3

    const int e     = g_mt_e[mt];
    const int tbase = g_mt_base[mt];
    const int tcnt  = g_mt_cnt[mt];

    if (tid < TM) {
        int i = (tid < tcnt) ? tid : (tcnt - 1);
        toks[tid] = g_sorted[tbase + i];
    }
    if (tid < TN) bias_s[tid] = g_bsum[e * 256 + nb * TN + tid];
    __syncthreads();

    const float* __restrict__ wsrc = g_wsum + (size_t)e * 65536 + (size_t)nb * (TN * 256);
    const uint32_t dsm_b = smem_u32(dsm);

    // staging roles: idx = tid + 256*i (i<4): row = idx>>3 (0..127), q = idx&7
    const int srow = tid >> 3;
    const int sq   = tid & 7;
    int stok[4];
    #pragma unroll
    for (int i = 0; i < 4; i++) stok[i] = toks[srow + 32 * i];

    // stage B chunk c into buffer b (cp.async, padded rows)
    auto stage_B = [&](int c, int b) {
        const uint32_t dst0 = dsm_b + (uint32_t)((2 + b) * TILE_F * 4);
        #pragma unroll
        for (int i = 0; i < 4; i++) {
            int o = srow + 32 * i;
            CP_ASYNC16(dst0 + (uint32_t)((o * RPAD + sq * 4) * 4),
                       wsrc + o * 256 + c * KC + sq * 4);
        }
        CP_COMMIT();
    };
    auto ldg_A = [&](int c, float4* v) {
        #pragma unroll
        for (int i = 0; i < 4; i++)
            v[i] = *(const float4*)(input + (size_t)stok[i] * 256 + c * KC + sq * 4);
    };
    auto sts_A = [&](int b, const float4* v) {
        float* dst = dsm + b * TILE_F;
        #pragma unroll
        for (int i = 0; i < 4; i++) {
            int m = srow + 32 * i;
            uint4 cv;
            cv.x = f2tf(v[i].x); cv.y = f2tf(v[i].y);
            cv.z = f2tf(v[i].z); cv.w = f2tf(v[i].w);
            *(uint4*)(dst + m * RPAD + sq * 4) = cv;
        }
    };

    float acc[2][8][4];
    #pragma unroll
    for (int am = 0; am < 2; am++)
        #pragma unroll
        for (int an = 0; an < 8; an++)
            #pragma unroll
            for (int j = 0; j < 4; j++) acc[am][an][j] = 0.0f;

    // fragment base offsets (floats)
    const int a_base = (wm * 32 + r0) * RPAD + kq;   // +576*am, +288 row+8, +4 k+4
    const int b_base = (wn * 64 + r0) * RPAD + kq;   // +288*an, +4 k+4

    // prologue
    stage_B(0, 0);
    {
        float4 av[4];
        ldg_A(0, av);
        sts_A(0, av);
    }

    #pragma unroll 1
    for (int c = 0; c < NCH; c++) {
        float4 av[4];
        const bool more = (c + 1 < NCH);
        if (more) {
            ldg_A(c + 1, av);          // in flight under compute
            stage_B(c + 1, (c + 1) & 1);
            CP_WAIT(1);                // B(c) landed
        } else {
            CP_WAIT(0);
        }
        __syncthreads();

        const float* Ab = dsm + (c & 1) * TILE_F;
        const float* Bb = dsm + (2 + (c & 1)) * TILE_F;
        const uint32_t* Au = (const uint32_t*)Ab;
        const uint32_t* Bu = (const uint32_t*)Bb;

        #pragma unroll
        for (int kk = 0; kk < 4; kk++) {
            const int ofs = kk * 8;
            uint32_t a[2][4];
            #pragma unroll
            for (int am = 0; am < 2; am++) {
                const int ab = a_base + am * 576 + ofs;
                a[am][0] = Au[ab];
                a[am][1] = Au[ab + 288];
                a[am][2] = Au[ab + 4];
                a[am][3] = Au[ab + 292];
            }
            #pragma unroll
            for (int an = 0; an < 8; an++) {
                const int bb = b_base + an * 288 + ofs;
                uint32_t b0 = Bu[bb];
                uint32_t b1 = Bu[bb + 4];
                mma_tf32(acc[0][an], a[0], b0, b1);
                mma_tf32(acc[1][an], a[1], b0, b1);
            }
        }
        __syncthreads();
        if (more) sts_A((c + 1) & 1, av);   // hidden behind compute latency
    }

    // epilogue: bias + store (float2 per atom-row)
    #pragma unroll
    for (int am = 0; am < 2; am++) {
        const int row0 = wm * 32 + am * 16 + r0;
        const int row1 = row0 + 8;
        const bool v0 = row0 < tcnt;
        const bool v1 = row1 < tcnt;
        float* const orow0 = out + (size_t)toks[row0] * 256 + nb * TN;
        float* const orow1 = out + (size_t)toks[row1] * 256 + nb * TN;
        #pragma unroll
        for (int an = 0; an < 8; an++) {
            const int col = wn * 64 + an * 8 + 2 * kq;
            const float bx = bias_s[col], by = bias_s[col + 1];
            if (v0) {
                float2 o0 = make_float2(acc[am][an][0] + bx, acc[am][an][1] + by);
                *(float2*)(orow0 + col) = o0;
            }
            if (v1) {
                float2 o1 = make_float2(acc[am][an][2] + bx, acc[am][an][3] + by);
                *(float2*)(orow1 + col) = o1;
            }
        }
    }
}

// ---------------------------------------------------------------------------
extern "C" void kernel_launch(void* const* d_in, const int* in_sizes, int n_in,
                              void* d_out, int out_size) {
    const float* input  = (const float*)d_in[0];
    const int*   route  = (const int*)d_in[1];
    const float* weight = (const float*)d_in[2];
    const float* wfact  = (const float*)d_in[3];
    const float* bias   = (const float*)d_in[4];
    const float* bfact  = (const float*)d_in[5];
    float* out = (float*)d_out;

    cudaFuncSetAttribute(switch_gemm, cudaFuncAttributeMaxDynamicSharedMemorySize,
                         DSMEM_BYTES);

    prep_kernel<<<129, 256>>>(route, weight, wfact, bias, bfact);
    switch_gemm<<<GRID_GEMM, 256, DSMEM_BYTES>>>(input, out);
}

// round 7
// speedup vs baseline: 1.8263x; 1.2452x over previous
#include <cuda_runtime.h>
#include <cstdint>

// SwitchLinear via portable tensor-core mma.sync (tf32), sm_103-safe PTX.
// out[t] = (W[route[t]] + Wf) @ x[t] + b[route[t]] + bf ; B=4096, IN=OUT=256, E=16.
//
// route_kernel (1 block, 1024 thr): histogram/scan/scatter into 64-token
//   m-tiles + g_bsum = bias + bfact.
// switch_gemm (<=160 blocks, 512 thr): tile = (64 tokens, 128 outs).
//   16 warps (4m x 4n), warp tile 16x32, mma.m16n8k8.tf32, fp32 accum.
//   W+Wf summed + tf32-rounded IN-KERNEL during B staging (no prep pass).
//   K chunks of 32, double-buffered smem, rows padded to 36 floats
//   (all fragment LDS conflict-free).

#define B_TOK   4096
#define E_NUM   16
#define TM      64
#define TN      128
#define KC      32
#define NCH     8
#define MAX_MT  80
#define GRID_GEMM 160
#define RPAD    36
#define A_TILE_F (TM * RPAD)             // 2304 floats
#define B_TILE_F (TN * RPAD)             // 4608 floats
#define DSMEM_BYTES ((2 * A_TILE_F + 2 * B_TILE_F) * 4)   // 55296 B

__device__ int   g_sorted[B_TOK];
__device__ int   g_mt_e[MAX_MT];
__device__ int   g_mt_base[MAX_MT];
__device__ int   g_mt_cnt[MAX_MT];
__device__ int   g_nmt;
__device__ float g_bsum[E_NUM * 256];

static __device__ __forceinline__ uint32_t f2tf(float x) {
    uint32_t u;
    asm("cvt.rna.tf32.f32 %0, %1;" : "=r"(u) : "f"(x));
    return u;
}

static __device__ __forceinline__ void mma_tf32(float* d, const uint32_t* a,
                                                uint32_t b0, uint32_t b1) {
    asm volatile(
        "mma.sync.aligned.m16n8k8.row.col.f32.tf32.tf32.f32 "
        "{%0,%1,%2,%3}, {%4,%5,%6,%7}, {%8,%9}, {%0,%1,%2,%3};"
        : "+f"(d[0]), "+f"(d[1]), "+f"(d[2]), "+f"(d[3])
        : "r"(a[0]), "r"(a[1]), "r"(a[2]), "r"(a[3]), "r"(b0), "r"(b1));
}

// ---------------------------------------------------------------------------
// routing
// ---------------------------------------------------------------------------
__global__ void route_kernel(const int* __restrict__ route,
                             const float* __restrict__ bias,
                             const float* __restrict__ bfact) {
    __shared__ int cnt[E_NUM];
    __shared__ int cur[E_NUM];
    const int tid  = threadIdx.x;
    const int lane = tid & 31;

    if (tid < E_NUM) cnt[tid] = 0;
    __syncthreads();

    for (int t = tid; t < B_TOK; t += 1024) {
        int e = route[t];
        unsigned m = __match_any_sync(0xffffffffu, e);
        int leader = __ffs(m) - 1;
        if (lane == leader) atomicAdd(&cnt[e], __popc(m));
    }
    __syncthreads();

    if (tid < 32) {
        int c  = (tid < E_NUM) ? cnt[tid] : 0;
        int nt = (c + TM - 1) / TM;
        int cs = c, ts = nt;
        #pragma unroll
        for (int d = 1; d < 32; d <<= 1) {
            int v = __shfl_up_sync(0xffffffffu, cs, d);
            int w = __shfl_up_sync(0xffffffffu, ts, d);
            if (lane >= d) { cs += v; ts += w; }
        }
        int coff = cs - c, toff = ts - nt;
        if (tid < E_NUM) {
            cur[tid] = coff;
            for (int j = 0; j < nt; j++) {
                g_mt_e[toff + j]    = tid;
                g_mt_base[toff + j] = coff + j * TM;
                int rem = c - j * TM;
                g_mt_cnt[toff + j]  = rem < TM ? rem : TM;
            }
            if (tid == E_NUM - 1) g_nmt = ts;
        }
    }
    __syncthreads();

    for (int t = tid; t < B_TOK; t += 1024) {
        int e = route[t];
        unsigned m = __match_any_sync(0xffffffffu, e);
        int leader = __ffs(m) - 1;
        int rank = __popc(m & ((1u << lane) - 1u));
        int base = 0;
        if (lane == leader) base = atomicAdd(&cur[e], __popc(m));
        base = __shfl_sync(m, base, leader);
        g_sorted[base + rank] = t;
    }

    for (int i = tid; i < E_NUM * 256; i += 1024)
        g_bsum[i] = bias[i] + bfact[i & 255];
}

// ---------------------------------------------------------------------------
// gemm
// ---------------------------------------------------------------------------
__global__ __launch_bounds__(512, 1)
void switch_gemm(const float* __restrict__ input,
                 const float* __restrict__ weight,
                 const float* __restrict__ wfact,
                 float* __restrict__ out) {
    const int mt = blockIdx.x >> 1;
    const int nb = blockIdx.x & 1;
    if (mt >= g_nmt) return;

    extern __shared__ float dsm[];
    // layout (floats): A0 [0,2304) A1 [2304,4608) B0 [4608,9216) B1 [9216,13824)
    float* const A_s[2] = { dsm, dsm + A_TILE_F };
    float* const B_s[2] = { dsm + 2 * A_TILE_F, dsm + 2 * A_TILE_F + B_TILE_F };
    __shared__ int   toks[TM];
    __shared__ float bias_s[TN];

    const int tid  = threadIdx.x;
    const int wid  = tid >> 5;
    const int lane = tid & 31;
    const int wm   = wid & 3;          // m-warp: rows wm*16..+15
    const int wn   = wid >> 2;         // n-warp: outs wn*32..+31
    const int r0   = lane >> 2;        // 0..7
    const int kq   = lane & 3;         // 0..3

    const int e     = g_mt_e[mt];
    const int tbase = g_mt_base[mt];
    const int tcnt  = g_mt_cnt[mt];

    if (tid < TM) {
        int i = (tid < tcnt) ? tid : (tcnt - 1);
        toks[tid] = g_sorted[tbase + i];
    }
    if (tid < TN) bias_s[tid] = g_bsum[e * 256 + nb * TN + tid];
    __syncthreads();

    // staging roles
    const int arow = tid >> 3, asq = tid & 7;       // A: 64 rows x 8 f4-cols
    const int brow = tid >> 2, bsq = tid & 3;       // B: 128 rows x 4 x (2 f4)
    const float* __restrict__ airow = input + (size_t)toks[arow] * 256;
    const float* __restrict__ wrow  = weight + (size_t)e * 65536 + (size_t)(nb * TN + brow) * 256;
    const float* __restrict__ frow  = wfact + (size_t)(nb * TN + brow) * 256;

    float4 rA, rB0, rB1, rF0, rF1;
    auto ldg = [&](int c) {
        rA  = *(const float4*)(airow + c * KC + asq * 4);
        rB0 = *(const float4*)(wrow + c * KC + bsq * 8);
        rB1 = *(const float4*)(wrow + c * KC + bsq * 8 + 4);
        rF0 = *(const float4*)(frow + c * KC + bsq * 8);
        rF1 = *(const float4*)(frow + c * KC + bsq * 8 + 4);
    };
    auto sts = [&](int b) {
        uint4 ca;
        ca.x = f2tf(rA.x); ca.y = f2tf(rA.y); ca.z = f2tf(rA.z); ca.w = f2tf(rA.w);
        *(uint4*)(A_s[b] + arow * RPAD + asq * 4) = ca;
        uint4 c0, c1;
        c0.x = f2tf(rB0.x + rF0.x); c0.y = f2tf(rB0.y + rF0.y);
        c0.z = f2tf(rB0.z + rF0.z); c0.w = f2tf(rB0.w + rF0.w);
        c1.x = f2tf(rB1.x + rF1.x); c1.y = f2tf(rB1.y + rF1.y);
        c1.z = f2tf(rB1.z + rF1.z); c1.w = f2tf(rB1.w + rF1.w);
        *(uint4*)(B_s[b] + brow * RPAD + bsq * 8)     = c0;
        *(uint4*)(B_s[b] + brow * RPAD + bsq * 8 + 4) = c1;
    };

    float acc[4][4];
    #pragma unroll
    for (int an = 0; an < 4; an++)
        #pragma unroll
        for (int j = 0; j < 4; j++) acc[an][j] = 0.0f;

    const int a_base = (wm * 16 + r0) * RPAD + kq;   // a1/a3 at +8*RPAD, k+4 at +4
    const int b_base = (wn * 32 + r0) * RPAD + kq;   // an at +8*RPAD

    // prologue
    ldg(0);
    sts(0);
    ldg(1);
    __syncthreads();

    #pragma unroll 1
    for (int c = 0; c < NCH; c++) {
        if (c + 1 < NCH) sts((c + 1) & 1);     // regs hold chunk c+1
        if (c + 2 < NCH) ldg(c + 2);

        const uint32_t* Au = (const uint32_t*)A_s[c & 1];
        const uint32_t* Bu = (const uint32_t*)B_s[c & 1];
        #pragma unroll
        for (int kk = 0; kk < 4; kk++) {
            const int ofs = kk * 8;
            uint32_t a[4];
            a[0] = Au[a_base + ofs];
            a[1] = Au[a_base + ofs + 8 * RPAD];
            a[2] = Au[a_base + ofs + 4];
            a[3] = Au[a_base + ofs + 8 * RPAD + 4];
            #pragma unroll
            for (int an = 0; an < 4; an++) {
                const int bb = b_base + an * 8 * RPAD + ofs;
                mma_tf32(acc[an], a, Bu[bb], Bu[bb + 4]);
            }
        }
        __syncthreads();
    }

    // epilogue: bias + store
    const int row0 = wm * 16 + r0;
    const int row1 = row0 + 8;
    const bool v0 = row0 < tcnt;
    const bool v1 = row1 < tcnt;
    float* const orow0 = out + (size_t)toks[row0] * 256 + nb * TN;
    float* const orow1 = out + (size_t)toks[row1] * 256 + nb * TN;
    #pragma unroll
    for (int an = 0; an < 4; an++) {
        const int col = wn * 32 + an * 8 + 2 * kq;
        const float bx = bias_s[col], by = bias_s[col + 1];
        if (v0) *(float2*)(orow0 + col) = make_float2(acc[an][0] + bx, acc[an][1] + by);
        if (v1) *(float2*)(orow1 + col) = make_float2(acc[an][2] + bx, acc[an][3] + by);
    }
}

// ---------------------------------------------------------------------------
extern "C" void kernel_launch(void* const* d_in, const int* in_sizes, int n_in,
                              void* d_out, int out_size) {
    const float* input  = (const float*)d_in[0];
    const int*   route  = (const int*)d_in[1];
    const float* weight = (const float*)d_in[2];
    const float* wfact  = (const float*)d_in[3];
    const float* bias   = (const float*)d_in[4];
    const float* bfact  = (const float*)d_in[5];
    float* out = (float*)d_out;

    cudaFuncSetAttribute(switch_gemm, cudaFuncAttributeMaxDynamicSharedMemorySize,
                         DSMEM_BYTES);

    route_kernel<<<1, 1024>>>(route, bias, bfact);
    switch_gemm<<<GRID_GEMM, 512, DSMEM_BYTES>>>(input, weight, wfact, out);
}